// round 7
// baseline (speedup 1.0000x reference)
#include <cuda_runtime.h>
#include <cuda_bf16.h>
#include <cstdint>

typedef unsigned long long u64;

#define BB 4
#define NN 4096
#define MM 4096
#define MT 128            // threads per block == m's per block
#define NT 512            // n's per chunk
#define NQ (NT / 2)       // packed pairs per chunk
#define NCHUNK (NN / NT)  // 8
#define MTILES (MM / MT)  // 32
#define NTILES (BB * MTILES)  // 128  (== MT, used for final reduce)

#define EPSF     1e-8f
#define INV_LN2  1.4426950408889634f
// 1.5 * ln(2*3.14159)  (reference uses pi = 3.14159)
#define C_OFF    2.7568143383208773f

__device__ float g_part[NCHUNK][BB * MM];
__device__ float g_tile[NTILES];
__device__ unsigned g_tilecnt[NTILES];
__device__ unsigned g_count = 0;

// ---------------- packed f32x2 primitives ----------------
#define FMA2(d, a, b, c) asm("fma.rn.f32x2 %0, %1, %2, %3;"  : "=l"(d) : "l"(a), "l"(b), "l"(c))
#define ADD2(d, a, b)    asm("add.rn.f32x2 %0, %1, %2;"      : "=l"(d) : "l"(a), "l"(b))

__device__ __forceinline__ u64 pk(float lo, float hi) {
    u64 r;
    asm("mov.b64 %0, {%1, %2};" : "=l"(r) : "f"(lo), "f"(hi));
    return r;
}

__device__ __forceinline__ float ex2f(float x) {
    float r;
    asm("ex2.approx.f32 %0, %1;" : "=f"(r) : "f"(x));
    return r;
}

// ------------- main: fused prep + pair sums + full reduction ---------------
__global__ __launch_bounds__(MT) void gmm_main_kernel(const float* __restrict__ xyz,
                                                      const float* __restrict__ sig,
                                                      const float* __restrict__ target,
                                                      float* __restrict__ out) {
    // per-q packed coefficient pairs: D12={cp,apx} D34={apy,bpz} D56={na,nb}
    __shared__ ulonglong2 sD12[NQ], sD34[NQ], sD56[NQ];
    __shared__ float red[MT];
    __shared__ bool tileLast, gridLast;

    const int mt = blockIdx.x;     // 0..MTILES-1
    const int ch = blockIdx.y;     // 0..NCHUNK-1
    const int b  = blockIdx.z;     // 0..BB-1
    const int tid = threadIdx.x;

    // ---- in-block prep: each thread preps NT/MT = 4 n's ----
    for (int jj = tid; jj < NT; jj += MT) {
        const int n = b * NN + ch * NT + jj;
        float px = xyz[3 * n + 0], py = xyz[3 * n + 1], pz = xyz[3 * n + 2];
        float sxy = sig[2 * n + 0] + EPSF;
        float sz  = sig[2 * n + 1] + EPSF;
        float a  = __fdividef(0.5f * INV_LN2, sxy);   // log2-domain coefs
        float bz = __fdividef(0.5f * INV_LN2, sz);
        float c  = (-__logf(sxy) - 0.5f * __logf(sz) - C_OFF) * INV_LN2;
        float cp  = c - a * (px * px + py * py) - bz * (pz * pz);
        float apx = 2.0f * a * px;
        float apy = 2.0f * a * py;
        float bpz = 2.0f * bz * pz;

        const int q = jj >> 1, par = jj & 1;
        float* f12 = (float*)sD12;       // lanes: [4q+0/1]=cp_{e,o} [4q+2/3]=apx_{e,o}
        float* f34 = (float*)sD34;
        float* f56 = (float*)sD56;
        f12[4 * q + 0 + par] = cp;
        f12[4 * q + 2 + par] = apx;
        f34[4 * q + 0 + par] = apy;
        f34[4 * q + 2 + par] = bpz;
        f56[4 * q + 0 + par] = -a;
        f56[4 * q + 2 + par] = -bz;
    }

    // ---- per-m values ----
    const int m = mt * MT + tid;
    const float* tp = target + ((size_t)b * MM + m) * 3;
    const float tx = tp[0], ty = tp[1], tz = tp[2];
    const u64 TX  = pk(tx, tx);
    const u64 TY  = pk(ty, ty);
    const u64 TZ  = pk(tz, tz);
    const u64 ST  = pk(tx * tx + ty * ty, tx * tx + ty * ty);
    const u64 TZ2 = pk(tz * tz, tz * tz);

    __syncthreads();

    u64 acc = 0ull;                       // packed {0.0f, 0.0f}

#pragma unroll 8
    for (int j = 0; j < NQ; j++) {
        ulonglong2 D12 = sD12[j], D34 = sD34[j], D56 = sD56[j];
        u64 x;

        FMA2(x, D12.y, TX, D12.x);        // cp + apx*tx
        FMA2(x, D34.x, TY, x);            // + apy*ty
        FMA2(x, D34.y, TZ, x);            // + bpz*tz
        FMA2(x, D56.x, ST, x);            // - a*|txy|^2
        FMA2(x, D56.y, TZ2, x);           // - bz*tz^2      (x = lp/ln2, packed)

        float xlo, xhi;
        asm("mov.b64 {%0, %1}, %2;" : "=f"(xlo), "=f"(xhi) : "l"(x));
        // MUFU pipe: exp2; flushes huge-negative to 0 natively
        float e0 = ex2f(xlo);
        float e1 = ex2f(xhi);
        u64 pe = pk(e0, e1);              // ALU-pipe repack
        ADD2(acc, pe, acc);               // one fma-pipe accumulate
    }

    float a0 = __uint_as_float((unsigned)acc);
    float a1 = __uint_as_float((unsigned)(acc >> 32));
    g_part[ch][b * MM + m] = a0 + a1;

    // ---- tile-level reduction: last chunk-block of this (b, mt) tile ----
    __threadfence();
    const int tile = b * MTILES + mt;
    if (tid == 0)
        tileLast = (atomicAdd(&g_tilecnt[tile], 1u) == NCHUNK - 1);
    __syncthreads();
    if (!tileLast) return;

    {
        float s = 0.0f;
#pragma unroll
        for (int c = 0; c < NCHUNK; c++) s += g_part[c][b * MM + m];
        red[tid] = -__logf(s);            // nll = -ln(sum e^lp), fixed order
    }
    __syncthreads();
    for (int st = MT / 2; st > 0; st >>= 1) {
        if (tid < st) red[tid] += red[tid + st];
        __syncthreads();
    }
    if (tid == 0) {
        g_tile[tile] = red[0];
        g_tilecnt[tile] = 0;              // reset for next graph replay
        __threadfence();
        gridLast = (atomicAdd(&g_count, 1u) == NTILES - 1);
    }
    __syncthreads();
    if (!gridLast) return;

    // ---- grid-level final: combine 128 tile sums, fixed order ----
    red[tid] = g_tile[tid];               // NTILES == MT
    __syncthreads();
    for (int st = NTILES / 2; st > 0; st >>= 1) {
        if (tid < st) red[tid] += red[tid + st];
        __syncthreads();
    }
    if (tid == 0) {
        out[0] = red[0] * (1.0f / (BB * MM));
        g_count = 0;                      // reset for next graph replay
    }
}

extern "C" void kernel_launch(void* const* d_in, const int* in_sizes, int n_in,
                              void* d_out, int out_size) {
    const float* pred_xyz   = (const float*)d_in[0];  // [B, N, 3]
    const float* pred_sigma = (const float*)d_in[1];  // [B, N, 2]
    const float* target     = (const float*)d_in[2];  // [B, M, 3]
    float* out = (float*)d_out;

    dim3 grid(MTILES, NCHUNK, BB);
    gmm_main_kernel<<<grid, MT>>>(pred_xyz, pred_sigma, target, out);
}

// round 8
// speedup vs baseline: 1.6138x; 1.6138x over previous
#include <cuda_runtime.h>
#include <cuda_bf16.h>
#include <cstdint>

typedef unsigned long long u64;

#define BB 4
#define NN 4096
#define MM 4096
#define MT 256            // threads per block == m's per block
#define NT 256            // n's per chunk (== MT: 1 prep per thread)
#define NQ (NT / 2)       // packed pairs per chunk = 128
#define NCHUNK (NN / NT)  // 16
#define RED_BLOCKS 128
#define RED_T 128

#define EPSF     1e-8f
#define INV_LN2  1.4426950408889634f
// 1.5 * ln(2*3.14159)  (reference uses pi = 3.14159)
#define C_OFF    2.7568143383208773f

// transposed partials: g_part[m_global][ch] -- 16 contiguous floats per m
__device__ float g_part[BB * MM][NCHUNK];
__device__ float g_red[RED_BLOCKS];
__device__ unsigned g_count = 0;

// ---------------- packed f32x2 primitives ----------------
#define FMA2(d, a, b, c) asm("fma.rn.f32x2 %0, %1, %2, %3;"  : "=l"(d) : "l"(a), "l"(b), "l"(c))
#define ADD2(d, a, b)    asm("add.rn.f32x2 %0, %1, %2;"      : "=l"(d) : "l"(a), "l"(b))

__device__ __forceinline__ u64 pk(float lo, float hi) {
    u64 r;
    asm("mov.b64 %0, {%1, %2};" : "=l"(r) : "f"(lo), "f"(hi));
    return r;
}

__device__ __forceinline__ float ex2f(float x) {
    float r;
    asm("ex2.approx.f32 %0, %1;" : "=f"(r) : "f"(x));
    return r;
}

// ---------------- main: fused prep + partial sum over one n-chunk ----------
__global__ __launch_bounds__(MT) void gmm_main_kernel(const float* __restrict__ xyz,
                                                      const float* __restrict__ sig,
                                                      const float* __restrict__ target) {
    // per-q packed coefficient pairs: D12={cp,apx} D34={apy,bpz} D56={na,nb}
    __shared__ ulonglong2 sD12[NQ], sD34[NQ], sD56[NQ];

    const int mt = blockIdx.x;     // 0..MM/MT-1
    const int ch = blockIdx.y;     // 0..NCHUNK-1
    const int b  = blockIdx.z;     // 0..BB-1
    const int tid = threadIdx.x;

    // ---- in-block prep: one n per thread (NT == MT) ----
    {
        const int n = b * NN + ch * NT + tid;
        float px = xyz[3 * n + 0], py = xyz[3 * n + 1], pz = xyz[3 * n + 2];
        float sxy = sig[2 * n + 0] + EPSF;
        float sz  = sig[2 * n + 1] + EPSF;
        float a  = __fdividef(0.5f * INV_LN2, sxy);   // log2-domain coefs
        float bz = __fdividef(0.5f * INV_LN2, sz);
        float c  = (-__logf(sxy) - 0.5f * __logf(sz) - C_OFF) * INV_LN2;
        float cp  = c - a * (px * px + py * py) - bz * (pz * pz);
        float apx = 2.0f * a * px;
        float apy = 2.0f * a * py;
        float bpz = 2.0f * bz * pz;

        const int q = tid >> 1, par = tid & 1;
        float* f12 = (float*)sD12;       // lanes: [4q+0/1]=cp_{e,o} [4q+2/3]=apx_{e,o}
        float* f34 = (float*)sD34;
        float* f56 = (float*)sD56;
        f12[4 * q + 0 + par] = cp;
        f12[4 * q + 2 + par] = apx;
        f34[4 * q + 0 + par] = apy;
        f34[4 * q + 2 + par] = bpz;
        f56[4 * q + 0 + par] = -a;
        f56[4 * q + 2 + par] = -bz;
    }

    // ---- per-m values ----
    const int m = mt * MT + tid;
    const float* tp = target + ((size_t)b * MM + m) * 3;
    const float tx = tp[0], ty = tp[1], tz = tp[2];
    const u64 TX  = pk(tx, tx);
    const u64 TY  = pk(ty, ty);
    const u64 TZ  = pk(tz, tz);
    const u64 ST  = pk(tx * tx + ty * ty, tx * tx + ty * ty);
    const u64 TZ2 = pk(tz * tz, tz * tz);

    __syncthreads();

    u64 acc = 0ull;                       // packed {0.0f, 0.0f}

#pragma unroll 8
    for (int j = 0; j < NQ; j++) {
        ulonglong2 D12 = sD12[j], D34 = sD34[j], D56 = sD56[j];
        u64 x;

        FMA2(x, D12.y, TX, D12.x);        // cp + apx*tx
        FMA2(x, D34.x, TY, x);            // + apy*ty
        FMA2(x, D34.y, TZ, x);            // + bpz*tz
        FMA2(x, D56.x, ST, x);            // - a*|txy|^2
        FMA2(x, D56.y, TZ2, x);           // - bz*tz^2      (x = lp/ln2, packed)

        float xlo, xhi;
        asm("mov.b64 {%0, %1}, %2;" : "=f"(xlo), "=f"(xhi) : "l"(x));
        // MUFU pipe: exp2; flushes huge-negative to 0 natively
        float e0 = ex2f(xlo);
        float e1 = ex2f(xhi);
        u64 pe = pk(e0, e1);              // repack (ALU)
        ADD2(acc, pe, acc);               // single fma-pipe accumulate
    }

    float a0 = __uint_as_float((unsigned)acc);
    float a1 = __uint_as_float((unsigned)(acc >> 32));
    g_part[b * MM + m][ch] = a0 + a1;     // transposed: coalesced for reader
}

// ---------- reduction: 128 blocks; last block finishes deterministically ----
__global__ __launch_bounds__(RED_T) void gmm_red_kernel(float* __restrict__ out) {
    __shared__ float red[RED_T];
    __shared__ bool amLast;
    const int tid = threadIdx.x;
    const int i = blockIdx.x * RED_T + tid;     // 0 .. BB*MM-1
    // 16 contiguous floats per m: 4 x LDG.128, MLP=4
    const float4* p = (const float4*)g_part[i];
    float4 v0 = p[0], v1 = p[1], v2 = p[2], v3 = p[3];
    float s = ((v0.x + v0.y) + (v0.z + v0.w))
            + ((v1.x + v1.y) + (v1.z + v1.w))
            + ((v2.x + v2.y) + (v2.z + v2.w))
            + ((v3.x + v3.y) + (v3.z + v3.w));
    red[tid] = -__logf(s);                      // nll = -ln(sum e^lp)
    __syncthreads();
    for (int st = RED_T / 2; st > 0; st >>= 1) {
        if (tid < st) red[tid] += red[tid + st];
        __syncthreads();
    }
    if (tid == 0) {
        g_red[blockIdx.x] = red[0];
        __threadfence();
        unsigned prev = atomicAdd(&g_count, 1u);
        amLast = (prev == RED_BLOCKS - 1);
    }
    __syncthreads();
    if (amLast) {
        red[tid] = g_red[tid];                  // RED_T == RED_BLOCKS
        __syncthreads();
        for (int st = RED_BLOCKS / 2; st > 0; st >>= 1) {
            if (tid < st) red[tid] += red[tid + st];
            __syncthreads();
        }
        if (tid == 0) {
            out[0] = red[0] * (1.0f / (BB * MM));
            g_count = 0;                        // reset for next graph replay
        }
    }
}

extern "C" void kernel_launch(void* const* d_in, const int* in_sizes, int n_in,
                              void* d_out, int out_size) {
    const float* pred_xyz   = (const float*)d_in[0];  // [B, N, 3]
    const float* pred_sigma = (const float*)d_in[1];  // [B, N, 2]
    const float* target     = (const float*)d_in[2];  // [B, M, 3]
    float* out = (float*)d_out;

    dim3 grid(MM / MT, NCHUNK, BB);
    gmm_main_kernel<<<grid, MT>>>(pred_xyz, pred_sigma, target);

    gmm_red_kernel<<<RED_BLOCKS, RED_T>>>(out);
}